// round 3
// baseline (speedup 1.0000x reference)
#include <cuda_runtime.h>
#include <cuda_bf16.h>

#define MAX_ATOMS 200000

// packed per-atom data: {charge*sqrt(ELE_FACTOR), sqrt(c6), 0.5*r0, unused}
__device__ float4 g_atom[MAX_ATOMS];

__global__ __launch_bounds__(256) void pack_atoms_kernel(
    const float* __restrict__ charge,
    const float* __restrict__ c6,
    const float* __restrict__ r0,
    int n)
{
    int i = blockIdx.x * blockDim.x + threadIdx.x;
    if (i >= n || i >= MAX_ATOMS) return;
    float4 v;
    v.x = charge[i] * 18.2226124f;   // sqrt(332.0637)
    v.y = sqrtf(c6[i]);
    v.z = 0.5f * r0[i];
    v.w = 0.0f;
    g_atom[i] = v;
}

// ---- per-edge physics ----
__device__ __forceinline__ void edge_compute(
    float dx, float dy, float dz,
    const float4& ai, const float4& aj,
    float& ecoul, float& cf, float& edisp, float& df)
{
    const float EWALD_F = 1.12837917f;
    const float EWALD_P = 0.3275911f;
    const float A0 = 0.254829592f, A1 = -0.284496736f, A2 = 1.421413741f,
                A3 = -1.453152027f, A4 = 1.061405429f;
    const float COUL_BETA = 18.7f;
    const float COUL_R0 = 2.2f;
    const float G_EWALD = 0.3f;
    const float DISP_C = 1.0f / 1000000.0f;
    const float R45_6 = 8303.765625f;   // 4.5^6

    float r2 = dx * dx + dy * dy + dz * dz;
    float rinv = rsqrtf(r2);
    float rij = r2 * rinv;
    float rinv2 = rinv * rinv;

    // ---- Coulomb ----
    float prefactor = ai.x * aj.x * rinv;

    float x = (COUL_BETA / COUL_R0) * (rij - COUL_R0);
    float ex = __expf(x);
    float damp = ex / (1.0f + ex);
    float sp = __logf(1.0f + ex) * (1.0f / COUL_BETA);
    float s = rij * (1.0f / COUL_R0) / (1.0f + sp);

    ecoul = prefactor * s;
    float fcoul = prefactor * damp * s * s;

    float grij = G_EWALD * rij;
    float expm2 = __expf(-grij * grij);
    float t = 1.0f / (1.0f + EWALD_P * grij);
    float erfc = t * (A0 + t * (A1 + t * (A2 + t * (A3 + t * A4)))) * expm2;
    ecoul += prefactor * (erfc - 1.0f);
    fcoul += prefactor * (erfc + EWALD_F * grij * expm2 - 1.0f);
    cf = fcoul * rinv2;

    // ---- Dispersion ----
    float c6ij = ai.y * aj.y;
    float r0ij = ai.z + aj.z;

    float r4 = r2 * r2;
    float r5 = r4 * rij;
    float r6 = r4 * r2 + R45_6;
    float r6inv = 1.0f / r6;

    float e = __expf(rij - 2.5f * r0ij);
    float einv = 1.0f / (1.0f + e);
    float cso = 0.85f + 0.82f * einv;

    edisp = -c6ij * r6inv * cso + c6ij * DISP_C;
    float fdisp = -6.0f * c6ij * r5 * r6inv * r6inv * cso
                  - c6ij * r6inv * (0.82f * e * einv * einv);
    df = fdisp * rinv;
}

// 4 edges per thread: all streaming I/O is float4/int4 coalesced.
__global__ __launch_bounds__(256) void bamboo_edge4_kernel(
    const int4* __restrict__ row4,
    const int4* __restrict__ col4,
    const float4* __restrict__ dij4,
    float* __restrict__ out,
    int E4, int E)
{
    int i = blockIdx.x * blockDim.x + threadIdx.x;
    if (i >= E4) return;

    int4 r = row4[i];
    int4 c = col4[i];

    float4 d0 = dij4[3 * i + 0];
    float4 d1 = dij4[3 * i + 1];
    float4 d2 = dij4[3 * i + 2];

    float4 a0 = g_atom[r.x], b0 = g_atom[c.x];
    float4 a1 = g_atom[r.y], b1 = g_atom[c.y];
    float4 a2 = g_atom[r.z], b2 = g_atom[c.z];
    float4 a3 = g_atom[r.w], b3 = g_atom[c.w];

    float ec0, cf0, ed0, df0;
    float ec1, cf1, ed1, df1;
    float ec2, cf2, ed2, df2;
    float ec3, cf3, ed3, df3;

    edge_compute(d0.x, d0.y, d0.z, a0, b0, ec0, cf0, ed0, df0);
    edge_compute(d0.w, d1.x, d1.y, a1, b1, ec1, cf1, ed1, df1);
    edge_compute(d1.z, d1.w, d2.x, a2, b2, ec2, cf2, ed2, df2);
    edge_compute(d2.y, d2.z, d2.w, a3, b3, ec3, cf3, ed3, df3);

    // ---- outputs: [ecoul E][coul_fij 3E][edisp E][disp_fij 3E] ----
    float4* ecoul_o = (float4*)out;
    float4* cfij_o  = (float4*)(out + (size_t)E);
    float4* edisp_o = (float4*)(out + (size_t)4 * E);
    float4* dfij_o  = (float4*)(out + (size_t)5 * E);

    ecoul_o[i] = make_float4(ec0, ec1, ec2, ec3);
    edisp_o[i] = make_float4(ed0, ed1, ed2, ed3);

    cfij_o[3 * i + 0] = make_float4(d0.x * cf0, d0.y * cf0, d0.z * cf0, d0.w * cf1);
    cfij_o[3 * i + 1] = make_float4(d1.x * cf1, d1.y * cf1, d1.z * cf2, d1.w * cf2);
    cfij_o[3 * i + 2] = make_float4(d2.x * cf2, d2.y * cf3, d2.z * cf3, d2.w * cf3);

    dfij_o[3 * i + 0] = make_float4(d0.x * df0, d0.y * df0, d0.z * df0, d0.w * df1);
    dfij_o[3 * i + 1] = make_float4(d1.x * df1, d1.y * df1, d1.z * df2, d1.w * df2);
    dfij_o[3 * i + 2] = make_float4(d2.x * df2, d2.y * df3, d2.z * df3, d2.w * df3);
}

// scalar tail for E % 4 leftovers
__global__ void bamboo_edge_tail_kernel(
    const int* __restrict__ row,
    const int* __restrict__ col,
    const float* __restrict__ dij,
    float* __restrict__ out,
    int start, int E)
{
    int i = start + blockIdx.x * blockDim.x + threadIdx.x;
    if (i >= E) return;

    float dx = dij[3 * i + 0];
    float dy = dij[3 * i + 1];
    float dz = dij[3 * i + 2];
    float4 ai = g_atom[row[i]];
    float4 aj = g_atom[col[i]];

    float ec, cf, ed, df;
    edge_compute(dx, dy, dz, ai, aj, ec, cf, ed, df);

    out[i] = ec;
    float* cfij_o = out + (size_t)E;
    float* dfij_o = out + (size_t)5 * E;
    out[(size_t)4 * E + i] = ed;
    cfij_o[3 * i + 0] = dx * cf;
    cfij_o[3 * i + 1] = dy * cf;
    cfij_o[3 * i + 2] = dz * cf;
    dfij_o[3 * i + 0] = dx * df;
    dfij_o[3 * i + 1] = dy * df;
    dfij_o[3 * i + 2] = dz * df;
}

extern "C" void kernel_launch(void* const* d_in, const int* in_sizes, int n_in,
                              void* d_out, int out_size)
{
    const int*   row    = (const int*)d_in[0];
    const int*   col    = (const int*)d_in[1];
    const float* dij    = (const float*)d_in[2];
    const float* charge = (const float*)d_in[3];
    const float* c6     = (const float*)d_in[4];
    const float* r0     = (const float*)d_in[5];
    float* out = (float*)d_out;

    int E = in_sizes[0];
    int n_atoms = in_sizes[3];
    int E4 = E / 4;
    int tail = E - 4 * E4;

    int threads = 256;
    pack_atoms_kernel<<<(n_atoms + threads - 1) / threads, threads>>>(charge, c6, r0, n_atoms);

    if (E4 > 0) {
        bamboo_edge4_kernel<<<(E4 + threads - 1) / threads, threads>>>(
            (const int4*)row, (const int4*)col, (const float4*)dij, out, E4, E);
    }
    if (tail > 0) {
        bamboo_edge_tail_kernel<<<1, 128>>>(row, col, dij, out, 4 * E4, E);
    }
}

// round 4
// speedup vs baseline: 1.0262x; 1.0262x over previous
#include <cuda_runtime.h>
#include <cuda_bf16.h>

#define MAX_ATOMS 200000

// packed per-atom data: {charge*sqrt(ELE_FACTOR), sqrt(c6), 0.5*r0, unused}
__device__ float4 g_atom[MAX_ATOMS];

__global__ __launch_bounds__(256) void pack_atoms_kernel(
    const float* __restrict__ charge,
    const float* __restrict__ c6,
    const float* __restrict__ r0,
    int n)
{
    int i = blockIdx.x * blockDim.x + threadIdx.x;
    if (i >= n || i >= MAX_ATOMS) return;
    float4 v;
    v.x = charge[i] * 18.2226124f;   // sqrt(332.0637)
    v.y = sqrtf(c6[i]);
    v.z = 0.5f * r0[i];
    v.w = 0.0f;
    g_atom[i] = v;
}

// ---- per-edge physics ----
__device__ __forceinline__ void edge_compute(
    float dx, float dy, float dz,
    const float4& ai, const float4& aj,
    float& ecoul, float& cf, float& edisp, float& df)
{
    const float EWALD_F = 1.12837917f;
    const float EWALD_P = 0.3275911f;
    const float A0 = 0.254829592f, A1 = -0.284496736f, A2 = 1.421413741f,
                A3 = -1.453152027f, A4 = 1.061405429f;
    const float COUL_BETA = 18.7f;
    const float COUL_R0 = 2.2f;
    const float G_EWALD = 0.3f;
    const float DISP_C = 1.0f / 1000000.0f;
    const float R45_6 = 8303.765625f;   // 4.5^6

    float r2 = dx * dx + dy * dy + dz * dz;
    float rinv = rsqrtf(r2);
    float rij = r2 * rinv;
    float rinv2 = rinv * rinv;

    // ---- Coulomb ----
    float prefactor = ai.x * aj.x * rinv;

    float x = (COUL_BETA / COUL_R0) * (rij - COUL_R0);
    float ex = __expf(x);
    float damp = ex / (1.0f + ex);
    float sp = __logf(1.0f + ex) * (1.0f / COUL_BETA);
    float s = rij * (1.0f / COUL_R0) / (1.0f + sp);

    ecoul = prefactor * s;
    float fcoul = prefactor * damp * s * s;

    float grij = G_EWALD * rij;
    float expm2 = __expf(-grij * grij);
    float t = 1.0f / (1.0f + EWALD_P * grij);
    float erfc = t * (A0 + t * (A1 + t * (A2 + t * (A3 + t * A4)))) * expm2;
    ecoul += prefactor * (erfc - 1.0f);
    fcoul += prefactor * (erfc + EWALD_F * grij * expm2 - 1.0f);
    cf = fcoul * rinv2;

    // ---- Dispersion ----
    float c6ij = ai.y * aj.y;
    float r0ij = ai.z + aj.z;

    float r4 = r2 * r2;
    float r5 = r4 * rij;
    float r6 = r4 * r2 + R45_6;
    float r6inv = 1.0f / r6;

    float e = __expf(rij - 2.5f * r0ij);
    float einv = 1.0f / (1.0f + e);
    float cso = 0.85f + 0.82f * einv;

    edisp = -c6ij * r6inv * cso + c6ij * DISP_C;
    float fdisp = -6.0f * c6ij * r5 * r6inv * r6inv * cso
                  - c6ij * r6inv * (0.82f * e * einv * einv);
    df = fdisp * rinv;
}

// 2 edges per thread: streaming I/O via int2/float2, gathers via float4.
__global__ __launch_bounds__(256) void bamboo_edge2_kernel(
    const int2* __restrict__ row2,
    const int2* __restrict__ col2,
    const float2* __restrict__ dij2,
    float* __restrict__ out,
    int Ep, int E)
{
    int i = blockIdx.x * blockDim.x + threadIdx.x;
    if (i >= Ep) return;

    int2 r = __ldcs(&row2[i]);
    int2 c = __ldcs(&col2[i]);

    float2 d0 = __ldcs(&dij2[3 * i + 0]);   // Ax, Ay
    float2 d1 = __ldcs(&dij2[3 * i + 1]);   // Az, Bx
    float2 d2 = __ldcs(&dij2[3 * i + 2]);   // By, Bz

    float4 a0 = g_atom[r.x], b0 = g_atom[c.x];
    float4 a1 = g_atom[r.y], b1 = g_atom[c.y];

    float ecA, cfA, edA, dfA;
    float ecB, cfB, edB, dfB;
    edge_compute(d0.x, d0.y, d1.x, a0, b0, ecA, cfA, edA, dfA);
    edge_compute(d1.y, d2.x, d2.y, a1, b1, ecB, cfB, edB, dfB);

    // ---- outputs: [ecoul E][coul_fij 3E][edisp E][disp_fij 3E] ----
    float2* ecoul_o = (float2*)out;
    float2* cfij_o  = (float2*)(out + (size_t)E);
    float2* edisp_o = (float2*)(out + (size_t)4 * E);
    float2* dfij_o  = (float2*)(out + (size_t)5 * E);

    __stcs(&ecoul_o[i], make_float2(ecA, ecB));
    __stcs(&edisp_o[i], make_float2(edA, edB));

    __stcs(&cfij_o[3 * i + 0], make_float2(d0.x * cfA, d0.y * cfA));
    __stcs(&cfij_o[3 * i + 1], make_float2(d1.x * cfA, d1.y * cfB));
    __stcs(&cfij_o[3 * i + 2], make_float2(d2.x * cfB, d2.y * cfB));

    __stcs(&dfij_o[3 * i + 0], make_float2(d0.x * dfA, d0.y * dfA));
    __stcs(&dfij_o[3 * i + 1], make_float2(d1.x * dfA, d1.y * dfB));
    __stcs(&dfij_o[3 * i + 2], make_float2(d2.x * dfB, d2.y * dfB));
}

// scalar tail for odd E
__global__ void bamboo_edge_tail_kernel(
    const int* __restrict__ row,
    const int* __restrict__ col,
    const float* __restrict__ dij,
    float* __restrict__ out,
    int start, int E)
{
    int i = start + blockIdx.x * blockDim.x + threadIdx.x;
    if (i >= E) return;

    float dx = dij[3 * i + 0];
    float dy = dij[3 * i + 1];
    float dz = dij[3 * i + 2];
    float4 ai = g_atom[row[i]];
    float4 aj = g_atom[col[i]];

    float ec, cf, ed, df;
    edge_compute(dx, dy, dz, ai, aj, ec, cf, ed, df);

    out[i] = ec;
    float* cfij_o = out + (size_t)E;
    float* dfij_o = out + (size_t)5 * E;
    out[(size_t)4 * E + i] = ed;
    cfij_o[3 * i + 0] = dx * cf;
    cfij_o[3 * i + 1] = dy * cf;
    cfij_o[3 * i + 2] = dz * cf;
    dfij_o[3 * i + 0] = dx * df;
    dfij_o[3 * i + 1] = dy * df;
    dfij_o[3 * i + 2] = dz * df;
}

extern "C" void kernel_launch(void* const* d_in, const int* in_sizes, int n_in,
                              void* d_out, int out_size)
{
    const int*   row    = (const int*)d_in[0];
    const int*   col    = (const int*)d_in[1];
    const float* dij    = (const float*)d_in[2];
    const float* charge = (const float*)d_in[3];
    const float* c6     = (const float*)d_in[4];
    const float* r0     = (const float*)d_in[5];
    float* out = (float*)d_out;

    int E = in_sizes[0];
    int n_atoms = in_sizes[3];
    int Ep = E / 2;
    int tail = E - 2 * Ep;

    int threads = 256;
    pack_atoms_kernel<<<(n_atoms + threads - 1) / threads, threads>>>(charge, c6, r0, n_atoms);

    if (Ep > 0) {
        bamboo_edge2_kernel<<<(Ep + threads - 1) / threads, threads>>>(
            (const int2*)row, (const int2*)col, (const float2*)dij, out, Ep, E);
    }
    if (tail > 0) {
        bamboo_edge_tail_kernel<<<1, 32>>>(row, col, dij, out, 2 * Ep, E);
    }
}

// round 5
// speedup vs baseline: 1.1059x; 1.0777x over previous
#include <cuda_runtime.h>
#include <cuda_bf16.h>

#define MAX_ATOMS 200000

// packed per-atom data: {charge*sqrt(ELE_FACTOR), sqrt(c6), 0.5*r0, unused}
__device__ float4 g_atom[MAX_ATOMS];

__global__ __launch_bounds__(256) void pack_atoms_kernel(
    const float* __restrict__ charge,
    const float* __restrict__ c6,
    const float* __restrict__ r0,
    int n)
{
    int i = blockIdx.x * blockDim.x + threadIdx.x;
    if (i >= n || i >= MAX_ATOMS) return;
    float4 v;
    v.x = charge[i] * 18.2226124f;   // sqrt(332.0637)
    v.y = sqrtf(c6[i]);
    v.z = 0.5f * r0[i];
    v.w = 0.0f;
    g_atom[i] = v;
}

__global__ __launch_bounds__(256) void bamboo_edge_kernel(
    const int* __restrict__ row,
    const int* __restrict__ col,
    const float* __restrict__ dij,
    float* __restrict__ out,
    int E)
{
    int i = blockIdx.x * blockDim.x + threadIdx.x;
    if (i >= E) return;

    // ---- constants ----
    const float EWALD_F = 1.12837917f;
    const float EWALD_P = 0.3275911f;
    const float A0 = 0.254829592f, A1 = -0.284496736f, A2 = 1.421413741f,
                A3 = -1.453152027f, A4 = 1.061405429f;
    const float COUL_BETA = 18.7f;
    const float COUL_R0 = 2.2f;
    const float G_EWALD = 0.3f;
    const float DISP_C = 1.0f / 1000000.0f;      // 1 / 10^6
    const float R45_6 = 8303.765625f;            // 4.5^6

    int ri = __ldcs(&row[i]);
    int ci = __ldcs(&col[i]);

    float dx = __ldcs(&dij[3 * i + 0]);
    float dy = __ldcs(&dij[3 * i + 1]);
    float dz = __ldcs(&dij[3 * i + 2]);

    // two wide random gathers (L2-resident table; default caching)
    float4 ai = g_atom[ri];
    float4 aj = g_atom[ci];

    float r2 = dx * dx + dy * dy + dz * dz;
    float rinv = rsqrtf(r2);
    float rij = r2 * rinv;          // |d|
    float rinv2 = rinv * rinv;

    // ---- Coulomb ----
    float prefactor = ai.x * aj.x * rinv;   // ELE_FACTOR folded into packed charges

    float x = (COUL_BETA / COUL_R0) * (rij - COUL_R0);   // in [-10.2, 66.4]
    float ex = __expf(x);
    float damp = ex / (1.0f + ex);                        // sigmoid(x)
    float sp = __logf(1.0f + ex) * (1.0f / COUL_BETA);    // softplus(beta*z)/beta
    float s = rij * (1.0f / COUL_R0) / (1.0f + sp);

    float ecoul = prefactor * s;
    float fcoul = prefactor * damp * s * s;

    // Ewald short-range erfc correction
    float grij = G_EWALD * rij;
    float expm2 = __expf(-grij * grij);
    float t = 1.0f / (1.0f + EWALD_P * grij);
    float erfc = t * (A0 + t * (A1 + t * (A2 + t * (A3 + t * A4)))) * expm2;
    ecoul += prefactor * (erfc - 1.0f);
    fcoul += prefactor * (erfc + EWALD_F * grij * expm2 - 1.0f);

    float cf = fcoul * rinv2;

    // ---- Dispersion (D3-CSO) ----
    float c6ij = ai.y * aj.y;       // sqrt(c6i)*sqrt(c6j)
    float r0ij = ai.z + aj.z;       // 0.5*(r0i + r0j)

    float r4 = r2 * r2;
    float r5 = r4 * rij;
    float r6 = r4 * r2 + R45_6;
    float r6inv = 1.0f / r6;

    float e = __expf(rij - 2.5f * r0ij);
    float einv = 1.0f / (1.0f + e);
    float cso = 0.85f + 0.82f * einv;

    float edisp = -c6ij * r6inv * cso + c6ij * DISP_C;
    float fdisp = -6.0f * c6ij * r5 * r6inv * r6inv * cso
                  - c6ij * r6inv * (0.82f * e * einv * einv);
    float df = fdisp * rinv;

    // ---- outputs: [ecoul E][coul_fij 3E][edisp E][disp_fij 3E] ----
    float* ecoul_o = out;
    float* cfij_o  = out + (size_t)E;
    float* edisp_o = out + (size_t)4 * E;
    float* dfij_o  = out + (size_t)5 * E;

    __stcs(&ecoul_o[i], ecoul);
    __stcs(&cfij_o[3 * i + 0], dx * cf);
    __stcs(&cfij_o[3 * i + 1], dy * cf);
    __stcs(&cfij_o[3 * i + 2], dz * cf);
    __stcs(&edisp_o[i], edisp);
    __stcs(&dfij_o[3 * i + 0], dx * df);
    __stcs(&dfij_o[3 * i + 1], dy * df);
    __stcs(&dfij_o[3 * i + 2], dz * df);
}

extern "C" void kernel_launch(void* const* d_in, const int* in_sizes, int n_in,
                              void* d_out, int out_size)
{
    const int*   row    = (const int*)d_in[0];
    const int*   col    = (const int*)d_in[1];
    const float* dij    = (const float*)d_in[2];
    const float* charge = (const float*)d_in[3];
    const float* c6     = (const float*)d_in[4];
    const float* r0     = (const float*)d_in[5];
    float* out = (float*)d_out;

    int E = in_sizes[0];
    int n_atoms = in_sizes[3];

    int threads = 256;
    pack_atoms_kernel<<<(n_atoms + threads - 1) / threads, threads>>>(charge, c6, r0, n_atoms);
    bamboo_edge_kernel<<<(E + threads - 1) / threads, threads>>>(row, col, dij, out, E);
}

// round 6
// speedup vs baseline: 1.1064x; 1.0005x over previous
#include <cuda_runtime.h>
#include <cuda_bf16.h>

#define MAX_ATOMS 200000

// packed per-atom data: {charge*sqrt(ELE_FACTOR), sqrt(c6), 0.5*r0, unused}
__device__ float4 g_atom[MAX_ATOMS];

// vectorized pack: 4 atoms per thread
__global__ __launch_bounds__(256) void pack_atoms_kernel(
    const float4* __restrict__ charge4,
    const float4* __restrict__ c64,
    const float4* __restrict__ r04,
    int n4, int n)
{
    int i = blockIdx.x * blockDim.x + threadIdx.x;
    if (i < n4) {
        float4 q = charge4[i];
        float4 c = c64[i];
        float4 r = r04[i];
        g_atom[4 * i + 0] = make_float4(q.x * 18.2226124f, sqrtf(c.x), 0.5f * r.x, 0.0f);
        g_atom[4 * i + 1] = make_float4(q.y * 18.2226124f, sqrtf(c.y), 0.5f * r.y, 0.0f);
        g_atom[4 * i + 2] = make_float4(q.z * 18.2226124f, sqrtf(c.z), 0.5f * r.z, 0.0f);
        g_atom[4 * i + 3] = make_float4(q.w * 18.2226124f, sqrtf(c.w), 0.5f * r.w, 0.0f);
    }
    // tail (n not multiple of 4)
    int t = 4 * n4 + i;
    if (i < (n - 4 * n4)) {
        const float* charge = (const float*)charge4;
        const float* c6 = (const float*)c64;
        const float* r0 = (const float*)r04;
        g_atom[t] = make_float4(charge[t] * 18.2226124f, sqrtf(c6[t]), 0.5f * r0[t], 0.0f);
    }
}

__global__ __launch_bounds__(256) void bamboo_edge_kernel(
    const int* __restrict__ row,
    const int* __restrict__ col,
    const float* __restrict__ dij,
    float* __restrict__ out,
    int E)
{
    int i = blockIdx.x * blockDim.x + threadIdx.x;

    // ---- constants ----
    const float EWALD_F = 1.12837917f;
    const float EWALD_P = 0.3275911f;
    const float A0 = 0.254829592f, A1 = -0.284496736f, A2 = 1.421413741f,
                A3 = -1.453152027f, A4 = 1.061405429f;
    const float COUL_BETA = 18.7f;
    const float COUL_R0 = 2.2f;
    const float G_EWALD = 0.3f;
    const float DISP_C = 1.0f / 1000000.0f;      // 1 / 10^6
    const float R45_6 = 8303.765625f;            // 4.5^6

    // ---- pre-sync portion: streaming loads independent of pack kernel ----
    int ri = 0, ci = 0;
    float dx = 0.f, dy = 0.f, dz = 0.f;
    bool active = (i < E);
    if (active) {
        ri = __ldcs(&row[i]);
        ci = __ldcs(&col[i]);
        dx = __ldcs(&dij[3 * i + 0]);
        dy = __ldcs(&dij[3 * i + 1]);
        dz = __ldcs(&dij[3 * i + 2]);
    }

    // wait for pack_atoms_kernel completion (PDL)
    cudaGridDependencySynchronize();

    if (!active) return;

    // two wide random gathers (L2-resident table)
    float4 ai = g_atom[ri];
    float4 aj = g_atom[ci];

    float r2 = dx * dx + dy * dy + dz * dz;
    float rinv = rsqrtf(r2);
    float rij = r2 * rinv;          // |d|
    float rinv2 = rinv * rinv;

    // ---- Coulomb ----
    float prefactor = ai.x * aj.x * rinv;   // ELE_FACTOR folded into packed charges

    float x = (COUL_BETA / COUL_R0) * (rij - COUL_R0);   // in [-10.2, 66.4]
    float ex = __expf(x);
    float damp = ex / (1.0f + ex);                        // sigmoid(x)
    float sp = __logf(1.0f + ex) * (1.0f / COUL_BETA);    // softplus(beta*z)/beta
    float s = rij * (1.0f / COUL_R0) / (1.0f + sp);

    float ecoul = prefactor * s;
    float fcoul = prefactor * damp * s * s;

    // Ewald short-range erfc correction
    float grij = G_EWALD * rij;
    float expm2 = __expf(-grij * grij);
    float t = 1.0f / (1.0f + EWALD_P * grij);
    float erfc = t * (A0 + t * (A1 + t * (A2 + t * (A3 + t * A4)))) * expm2;
    ecoul += prefactor * (erfc - 1.0f);
    fcoul += prefactor * (erfc + EWALD_F * grij * expm2 - 1.0f);

    float cf = fcoul * rinv2;

    // ---- Dispersion (D3-CSO) ----
    float c6ij = ai.y * aj.y;       // sqrt(c6i)*sqrt(c6j)
    float r0ij = ai.z + aj.z;       // 0.5*(r0i + r0j)

    float r4 = r2 * r2;
    float r5 = r4 * rij;
    float r6 = r4 * r2 + R45_6;
    float r6inv = 1.0f / r6;

    float e = __expf(rij - 2.5f * r0ij);
    float einv = 1.0f / (1.0f + e);
    float cso = 0.85f + 0.82f * einv;

    float edisp = -c6ij * r6inv * cso + c6ij * DISP_C;
    float fdisp = -6.0f * c6ij * r5 * r6inv * r6inv * cso
                  - c6ij * r6inv * (0.82f * e * einv * einv);
    float df = fdisp * rinv;

    // ---- outputs: [ecoul E][coul_fij 3E][edisp E][disp_fij 3E] ----
    float* ecoul_o = out;
    float* cfij_o  = out + (size_t)E;
    float* edisp_o = out + (size_t)4 * E;
    float* dfij_o  = out + (size_t)5 * E;

    __stcs(&ecoul_o[i], ecoul);
    __stcs(&cfij_o[3 * i + 0], dx * cf);
    __stcs(&cfij_o[3 * i + 1], dy * cf);
    __stcs(&cfij_o[3 * i + 2], dz * cf);
    __stcs(&edisp_o[i], edisp);
    __stcs(&dfij_o[3 * i + 0], dx * df);
    __stcs(&dfij_o[3 * i + 1], dy * df);
    __stcs(&dfij_o[3 * i + 2], dz * df);
}

extern "C" void kernel_launch(void* const* d_in, const int* in_sizes, int n_in,
                              void* d_out, int out_size)
{
    const int*   row    = (const int*)d_in[0];
    const int*   col    = (const int*)d_in[1];
    const float* dij    = (const float*)d_in[2];
    const float* charge = (const float*)d_in[3];
    const float* c6     = (const float*)d_in[4];
    const float* r0     = (const float*)d_in[5];
    float* out = (float*)d_out;

    int E = in_sizes[0];
    int n_atoms = in_sizes[3];
    int n4 = n_atoms / 4;

    int threads = 256;
    int pack_blocks = (n4 + threads - 1) / threads;
    if (pack_blocks < 1) pack_blocks = 1;
    pack_atoms_kernel<<<pack_blocks, threads>>>(
        (const float4*)charge, (const float4*)c6, (const float4*)r0, n4, n_atoms);

    // edge kernel launched with Programmatic Dependent Launch: its pre-sync
    // portion (streaming loads) overlaps the tail of pack_atoms_kernel.
    cudaLaunchConfig_t cfg = {};
    cfg.gridDim = dim3((E + threads - 1) / threads, 1, 1);
    cfg.blockDim = dim3(threads, 1, 1);
    cfg.dynamicSmemBytes = 0;
    cfg.stream = 0;
    cudaLaunchAttribute attr[1];
    attr[0].id = cudaLaunchAttributeProgrammaticStreamSerialization;
    attr[0].val.programmaticStreamSerializationAllowed = 1;
    cfg.attrs = attr;
    cfg.numAttrs = 1;
    cudaLaunchKernelEx(&cfg, bamboo_edge_kernel, row, col, dij, out, E);
}